// round 2
// baseline (speedup 1.0000x reference)
#include <cuda_runtime.h>

#define Bb  16
#define H4  4096
#define KC  64          // k-chunk per block
#define NKC 16          // 1024 / KC
#define NSPLIT 32       // NKC * 2 matrices
#define TPB 256
#define BPH 8           // batches per thread (half of Bb)

// scratch: split-K partials [NSPLIT][B][4H] (8 MB) and reduced pre-activations
__device__ float g_part[(size_t)NSPLIT * Bb * H4];
__device__ float g_ifgo[(size_t)Bb * H4];

__device__ __forceinline__ unsigned long long pack2(float lo, float hi) {
    unsigned long long r;
    asm("mov.b64 %0, {%1, %2};" : "=l"(r) : "f"(lo), "f"(hi));
    return r;
}
__device__ __forceinline__ unsigned long long fma2(unsigned long long a,
                                                   unsigned long long b,
                                                   unsigned long long c) {
    unsigned long long d;
    asm("fma.rn.f32x2 %0, %1, %2, %3;" : "=l"(d) : "l"(a), "l"(b), "l"(c));
    return d;
}
__device__ __forceinline__ void unpack2(unsigned long long v, float& lo, float& hi) {
    asm("mov.b64 {%0, %1}, %2;" : "=f"(lo), "=f"(hi) : "l"(v));
}

// ---------------------------------------------------------------------------
// Kernel 1: split-K GEMM partials.
// grid = (8 j-tiles, 16 k-chunks, 2 matrices), block = 256 threads.
// Threads 0-127 handle batches 0-7, threads 128-255 handle batches 8-15.
// Each thread: 4 consecutive output columns (LDG.128 weights) x 8 batches,
// 16 f32x2 accumulators via FFMA2.
// ---------------------------------------------------------------------------
__global__ __launch_bounds__(TPB) void gemm_part(
    const float* __restrict__ Wi, const float* __restrict__ Wh,
    const float* __restrict__ x,  const float* __restrict__ h)
{
    // activations duplicated {a,a}; layout [k][b], row = 16 ull = 128 B
    __shared__ unsigned long long sh[KC][Bb];

    const int jt  = blockIdx.x;   // 0..7
    const int kc  = blockIdx.y;   // 0..15
    const int mat = blockIdx.z;   // 0: Wi/x, 1: Wh/h
    const float* __restrict__ W   = mat ? Wh : Wi;
    const float* __restrict__ act = mat ? h  : x;
    const int k0   = kc * KC;
    const int tid  = threadIdx.x;
    const int lane = tid & 127;       // column-group id
    const int b0   = (tid >> 7) * BPH; // 0 or 8

    // stage activation chunk (1024 values), duplicated into both f32x2 lanes
    for (int i = tid; i < Bb * KC; i += TPB) {
        int k = i >> 4;
        int b = i & 15;
        float v = act[b * 1024 + k0 + k];
        sh[k][b] = pack2(v, v);
    }
    __syncthreads();

    const int j0 = jt * (128 * 4) + lane * 4;
    const float* Wp = W + (size_t)k0 * H4 + j0;

    unsigned long long acc[BPH][2];
#pragma unroll
    for (int b = 0; b < BPH; b++) { acc[b][0] = 0ull; acc[b][1] = 0ull; }

#pragma unroll 4
    for (int k = 0; k < KC; k++) {
        float4 w = *reinterpret_cast<const float4*>(Wp + (size_t)k * H4);
        unsigned long long wlo = pack2(w.x, w.y);
        unsigned long long whi = pack2(w.z, w.w);
#pragma unroll
        for (int bi = 0; bi < BPH; bi += 2) {
            // one LDS.128 pulls two duplicated activation pairs
            ulonglong2 a2 = *reinterpret_cast<const ulonglong2*>(&sh[k][b0 + bi]);
            acc[bi][0]     = fma2(wlo, a2.x, acc[bi][0]);
            acc[bi][1]     = fma2(whi, a2.x, acc[bi][1]);
            acc[bi + 1][0] = fma2(wlo, a2.y, acc[bi + 1][0]);
            acc[bi + 1][1] = fma2(whi, a2.y, acc[bi + 1][1]);
        }
    }

    const int s = mat * NKC + kc;
    float* outp = g_part + ((size_t)s * Bb + b0) * H4 + j0;
#pragma unroll
    for (int b = 0; b < BPH; b++) {
        float f0, f1, f2, f3;
        unpack2(acc[b][0], f0, f1);
        unpack2(acc[b][1], f2, f3);
        *reinterpret_cast<float4*>(outp + (size_t)b * H4) = make_float4(f0, f1, f2, f3);
    }
}

// ---------------------------------------------------------------------------
// Kernel 2: reduce 32 partials + biases -> g_ifgo
// ---------------------------------------------------------------------------
__global__ __launch_bounds__(256) void reduce_bias(
    const float* __restrict__ Wib, const float* __restrict__ Whb)
{
    int idx = blockIdx.x * blockDim.x + threadIdx.x;   // 0 .. B*4H
    int j = idx & (H4 - 1);
    float v = Wib[j] + Whb[j];
#pragma unroll
    for (int s = 0; s < NSPLIT; s++)
        v += g_part[(size_t)s * Bb * H4 + idx];
    g_ifgo[idx] = v;
}

// ---------------------------------------------------------------------------
// Kernel 3: LSTM gates + state update.  out = [h_new (B*H) | c_new (B*H)]
// ---------------------------------------------------------------------------
__global__ __launch_bounds__(256) void gates_kernel(
    const float* __restrict__ c, float* __restrict__ out)
{
    int idx = blockIdx.x * blockDim.x + threadIdx.x;   // 0 .. B*H
    int b = idx >> 10;
    int n = idx & 1023;
    const float* row = g_ifgo + (size_t)b * H4;
    float iv = row[n];
    float fv = row[1024 + n];
    float gv = row[2048 + n];
    float ov = row[3072 + n];
    float ig = 1.0f / (1.0f + expf(-iv));
    float fg = 1.0f / (1.0f + expf(-fv));
    float gg = tanhf(gv);
    float og = 1.0f / (1.0f + expf(-ov));
    float cn = fg * c[idx] + ig * gg;
    float hn = og * tanhf(cn);
    out[idx] = hn;
    out[Bb * 1024 + idx] = cn;
}

// ---------------------------------------------------------------------------
// Inputs (metadata order): x, h, c, context, Wi, Wi_b, Wh, Wh_b, AZ_il, AZ_ir,
// AZ_hl, AZ_hr.  context / AZ_* are dead (multiplied by 0 in the reference).
// ---------------------------------------------------------------------------
extern "C" void kernel_launch(void* const* d_in, const int* in_sizes, int n_in,
                              void* d_out, int out_size)
{
    (void)in_sizes; (void)n_in; (void)out_size;
    const float* x   = (const float*)d_in[0];
    const float* h   = (const float*)d_in[1];
    const float* c   = (const float*)d_in[2];
    const float* Wi  = (const float*)d_in[4];
    const float* Wib = (const float*)d_in[5];
    const float* Wh  = (const float*)d_in[6];
    const float* Whb = (const float*)d_in[7];
    float* out = (float*)d_out;

    dim3 g1(8, NKC, 2);
    gemm_part<<<g1, TPB>>>(Wi, Wh, x, h);
    reduce_bias<<<(Bb * H4) / 256, 256>>>(Wib, Whb);
    gates_kernel<<<(Bb * 1024) / 256, 256>>>(c, out);
}

// round 3
// speedup vs baseline: 1.0917x; 1.0917x over previous
#include <cuda_runtime.h>

#define Bb  16
#define H4  4096
#define KC  64          // k-chunk per block
#define NKC 16          // 1024 / KC
#define NSPLIT 32       // NKC * 2 matrices
#define TPB 256
#define BPH 8           // batches per thread (half of Bb)
#define PD  8           // LDG prefetch depth (register double-buffer)

// scratch: split-K partials [NSPLIT][B][4H] (8 MB) and reduced pre-activations
__device__ float g_part[(size_t)NSPLIT * Bb * H4];
__device__ float g_ifgo[(size_t)Bb * H4];

__device__ __forceinline__ unsigned long long pack2(float lo, float hi) {
    unsigned long long r;
    asm("mov.b64 %0, {%1, %2};" : "=l"(r) : "f"(lo), "f"(hi));
    return r;
}
__device__ __forceinline__ unsigned long long fma2(unsigned long long a,
                                                   unsigned long long b,
                                                   unsigned long long c) {
    unsigned long long d;
    asm("fma.rn.f32x2 %0, %1, %2, %3;" : "=l"(d) : "l"(a), "l"(b), "l"(c));
    return d;
}
__device__ __forceinline__ void unpack2(unsigned long long v, float& lo, float& hi) {
    asm("mov.b64 {%0, %1}, %2;" : "=f"(lo), "=f"(hi) : "l"(v));
}

// ---------------------------------------------------------------------------
// Kernel 1: split-K GEMM partials, software-pipelined weight stream.
// grid = (8 j-tiles, 16 k-chunks, 2 matrices), block = 256 threads.
// Threads 0-127: batches 0-7; threads 128-255: batches 8-15.
// Per thread: 4 output columns x 8 batches (16 f32x2 accs), PD=8 float4
// weight prefetch buffers keep 4KB/warp of LDG.128 in flight.
// ---------------------------------------------------------------------------
__global__ __launch_bounds__(TPB, 2) void gemm_part(
    const float* __restrict__ Wi, const float* __restrict__ Wh,
    const float* __restrict__ x,  const float* __restrict__ h)
{
    // activations duplicated {a,a}; layout [k][b], row = 16 ull = 128 B
    __shared__ unsigned long long sh[KC][Bb];

    const int jt  = blockIdx.x;   // 0..7
    const int kc  = blockIdx.y;   // 0..15
    const int mat = blockIdx.z;   // 0: Wi/x, 1: Wh/h
    const float* __restrict__ W   = mat ? Wh : Wi;
    const float* __restrict__ act = mat ? h  : x;
    const int k0   = kc * KC;
    const int tid  = threadIdx.x;
    const int lane = tid & 127;        // column-group id
    const int b0   = (tid >> 7) * BPH; // 0 or 8

    // stage activation chunk (1024 values), duplicated into both f32x2 lanes
    for (int i = tid; i < Bb * KC; i += TPB) {
        int k = i >> 4;
        int b = i & 15;
        float v = act[b * 1024 + k0 + k];
        sh[k][b] = pack2(v, v);
    }

    const int j0 = jt * (128 * 4) + lane * 4;
    const float* Wp = W + (size_t)k0 * H4 + j0;

    // prologue: fill PD prefetch buffers (independent of __syncthreads)
    float4 buf[PD];
#pragma unroll
    for (int p = 0; p < PD; p++)
        buf[p] = *reinterpret_cast<const float4*>(Wp + (size_t)p * H4);

    unsigned long long acc[BPH][2];
#pragma unroll
    for (int b = 0; b < BPH; b++) { acc[b][0] = 0ull; acc[b][1] = 0ull; }

    __syncthreads();

#pragma unroll
    for (int kk = 0; kk < KC; kk += PD) {
#pragma unroll
        for (int p = 0; p < PD; p++) {
            float4 w = buf[p];
            if (kk + PD < KC)   // compile-time predicate (kk unrolled)
                buf[p] = *reinterpret_cast<const float4*>(
                    Wp + (size_t)(kk + PD + p) * H4);
            unsigned long long wlo = pack2(w.x, w.y);
            unsigned long long whi = pack2(w.z, w.w);
            const int k = kk + p;
#pragma unroll
            for (int bi = 0; bi < BPH; bi += 2) {
                // one LDS.128 pulls two duplicated activation pairs (broadcast)
                ulonglong2 a2 = *reinterpret_cast<const ulonglong2*>(&sh[k][b0 + bi]);
                acc[bi][0]     = fma2(wlo, a2.x, acc[bi][0]);
                acc[bi][1]     = fma2(whi, a2.x, acc[bi][1]);
                acc[bi + 1][0] = fma2(wlo, a2.y, acc[bi + 1][0]);
                acc[bi + 1][1] = fma2(whi, a2.y, acc[bi + 1][1]);
            }
        }
    }

    const int s = mat * NKC + kc;
    float* outp = g_part + ((size_t)s * Bb + b0) * H4 + j0;
#pragma unroll
    for (int b = 0; b < BPH; b++) {
        float f0, f1, f2, f3;
        unpack2(acc[b][0], f0, f1);
        unpack2(acc[b][1], f2, f3);
        *reinterpret_cast<float4*>(outp + (size_t)b * H4) = make_float4(f0, f1, f2, f3);
    }
}

// ---------------------------------------------------------------------------
// Kernel 2: reduce 32 partials + biases -> g_ifgo
// ---------------------------------------------------------------------------
__global__ __launch_bounds__(256) void reduce_bias(
    const float* __restrict__ Wib, const float* __restrict__ Whb)
{
    int idx = blockIdx.x * blockDim.x + threadIdx.x;   // 0 .. B*4H
    int j = idx & (H4 - 1);
    float v = Wib[j] + Whb[j];
#pragma unroll
    for (int s = 0; s < NSPLIT; s++)
        v += g_part[(size_t)s * Bb * H4 + idx];
    g_ifgo[idx] = v;
}

// ---------------------------------------------------------------------------
// Kernel 3: LSTM gates + state update.  out = [h_new (B*H) | c_new (B*H)]
// ---------------------------------------------------------------------------
__global__ __launch_bounds__(256) void gates_kernel(
    const float* __restrict__ c, float* __restrict__ out)
{
    int idx = blockIdx.x * blockDim.x + threadIdx.x;   // 0 .. B*H
    int b = idx >> 10;
    int n = idx & 1023;
    const float* row = g_ifgo + (size_t)b * H4;
    float iv = row[n];
    float fv = row[1024 + n];
    float gv = row[2048 + n];
    float ov = row[3072 + n];
    float ig = 1.0f / (1.0f + expf(-iv));
    float fg = 1.0f / (1.0f + expf(-fv));
    float gg = tanhf(gv);
    float og = 1.0f / (1.0f + expf(-ov));
    float cn = fg * c[idx] + ig * gg;
    float hn = og * tanhf(cn);
    out[idx] = hn;
    out[Bb * 1024 + idx] = cn;
}

// ---------------------------------------------------------------------------
// Inputs (metadata order): x, h, c, context, Wi, Wi_b, Wh, Wh_b, AZ_il, AZ_ir,
// AZ_hl, AZ_hr.  context / AZ_* are dead (multiplied by 0 in the reference).
// ---------------------------------------------------------------------------
extern "C" void kernel_launch(void* const* d_in, const int* in_sizes, int n_in,
                              void* d_out, int out_size)
{
    (void)in_sizes; (void)n_in; (void)out_size;
    const float* x   = (const float*)d_in[0];
    const float* h   = (const float*)d_in[1];
    const float* c   = (const float*)d_in[2];
    const float* Wi  = (const float*)d_in[4];
    const float* Wib = (const float*)d_in[5];
    const float* Wh  = (const float*)d_in[6];
    const float* Whb = (const float*)d_in[7];
    float* out = (float*)d_out;

    dim3 g1(8, NKC, 2);
    gemm_part<<<g1, TPB>>>(Wi, Wh, x, h);
    reduce_bias<<<(Bb * H4) / 256, 256>>>(Wib, Whb);
    gates_kernel<<<(Bb * 1024) / 256, 256>>>(c, out);
}